// round 8
// baseline (speedup 1.0000x reference)
#include <cuda_runtime.h>
#include <cuda_fp16.h>
#include <cstdint>

#define CHARS   10000
#define HIDDEN  1024
#define OUTPUT  100
#define BATCH   4096
#define MAXLEN  2048

#define K_PAD   10240
#define NPAD    128
#define PPITCH  104                   // g_part row pitch (floats)
#define NSLICE  8
#define K_SLICE (K_PAD / NSLICE)      // 1280
#define NCHUNK_MAIN (K_SLICE / 64)    // 20
#define NCHUNK_WC   (HIDDEN / 64)     // 16

// ---------------- device scratch (static; allocations are banned) --------
__device__ __half  g_hist[(size_t)BATCH * K_PAD];           // 84 MB
__device__ __half  g_w1f[(size_t)HIDDEN * K_PAD];           // 21 MB
__device__ __half  g_w2f[(size_t)NPAD * HIDDEN];            // 256 KB
__device__ __half  g_wcf[(size_t)NPAD * K_PAD];             // 2.6 MB
__device__ float   g_part[(size_t)NSLICE * BATCH * PPITCH]; // 13.6 MB
__device__ float   g_bc[OUTPUT];

// ---------------- PTX helpers (portable sm_80-class only) ----------------
__device__ __forceinline__ uint32_t smem_u32(const void* p) {
    uint32_t a;
    asm("{ .reg .u64 t; cvta.to.shared.u64 t, %1; cvt.u32.u64 %0, t; }"
        : "=r"(a) : "l"(p));
    return a;
}

__device__ __forceinline__ void cp16(uint32_t s, const void* g) {
    asm volatile("cp.async.cg.shared.global [%0], [%1], 16;" :: "r"(s), "l"(g));
}
#define CP_COMMIT() asm volatile("cp.async.commit_group;" ::: "memory")
#define CP_WAIT2()  asm volatile("cp.async.wait_group 2;"  ::: "memory")

__device__ __forceinline__ void ldsm4(uint32_t* r, uint32_t a) {
    asm volatile("ldmatrix.sync.aligned.m8n8.x4.shared.b16 {%0,%1,%2,%3}, [%4];"
        : "=r"(r[0]), "=r"(r[1]), "=r"(r[2]), "=r"(r[3]) : "r"(a));
}
__device__ __forceinline__ void ldsm4t(uint32_t* r, uint32_t a) {
    asm volatile("ldmatrix.sync.aligned.m8n8.x4.trans.shared.b16 {%0,%1,%2,%3}, [%4];"
        : "=r"(r[0]), "=r"(r[1]), "=r"(r[2]), "=r"(r[3]) : "r"(a));
}

// D(16x8,f32) += A(16x16,f16) @ B(16x8,f16)
__device__ __forceinline__ void mma_f16(float* c, const uint32_t* a, const uint32_t* b) {
    asm volatile(
        "mma.sync.aligned.m16n8k16.row.col.f32.f16.f16.f32 "
        "{%0,%1,%2,%3}, {%4,%5,%6,%7}, {%8,%9}, {%0,%1,%2,%3};"
        : "+f"(c[0]), "+f"(c[1]), "+f"(c[2]), "+f"(c[3])
        : "r"(a[0]), "r"(a[1]), "r"(a[2]), "r"(a[3]), "r"(b[0]), "r"(b[1]));
}

// smem pitch (bytes) for 64-col 16-bit rows, +8 elem pad
#define PA 144

// ---------------- kernel 1a: per-row histogram -> fp16 (stream 0) --------
__global__ void __launch_bounds__(256) hist_kernel(const int* __restrict__ words) {
    __shared__ unsigned cnt[K_PAD / 2];
    const int bid = blockIdx.x, tid = threadIdx.x;
    for (int i = tid; i < K_PAD / 2; i += 256) cnt[i] = 0u;
    __syncthreads();
    const int* w = words + (size_t)bid * MAXLEN;
    #pragma unroll 8
    for (int j = tid; j < MAXLEN; j += 256) {
        unsigned c = (unsigned)w[j];
        atomicAdd(&cnt[c >> 1], 1u << ((c & 1u) * 16));
    }
    __syncthreads();
    __half2* out = (__half2*)(g_hist + (size_t)bid * K_PAD);
    for (int i = tid; i < K_PAD / 2; i += 256) {
        unsigned v = cnt[i];
        out[i] = __floats2half2_rn((float)(v & 0xFFFFu), (float)(v >> 16));
    }
}

// ---------------- kernel 1b: conversions + bc (stream 2) -----------------
#define NB_W1 1024
#define NB_W2 512
#define NB_BC 13
#define NB_CONV (NB_W1 + NB_W2 + NB_BC)

__global__ void __launch_bounds__(256) conv_kernel(
        const float* __restrict__ W1, const float* __restrict__ b1,
        const float* __restrict__ W2, const float* __restrict__ b2) {
    const int bid = blockIdx.x, tid = threadIdx.x;
    if (bid < NB_W1) {
        const float* src = W1 + (size_t)bid * CHARS;
        __half2* dst = (__half2*)(g_w1f + (size_t)bid * K_PAD);
        for (int i = tid; i < K_PAD / 2; i += 256) {
            float2 v = (i < CHARS / 2) ? *(const float2*)(src + 2 * i)
                                       : make_float2(0.f, 0.f);
            dst[i] = __floats2half2_rn(v.x, v.y);
        }
    } else if (bid < NB_W1 + NB_W2) {
        unsigned i = (bid - NB_W1) * 256u + tid;
        unsigned o = i >> 10;
        float v = (o < OUTPUT) ? W2[(size_t)o * HIDDEN + (i & 1023u)] : 0.f;
        g_w2f[i] = __float2half_rn(v);
    } else {
        int o = (bid - NB_W1 - NB_W2) * 8 + (tid >> 5);
        if (o < OUTPUT) {
            int lane = tid & 31;
            const float* w = W2 + (size_t)o * HIDDEN;
            float s = 0.f;
            #pragma unroll 8
            for (int h = lane; h < HIDDEN; h += 32) s += w[h] * b1[h];
            #pragma unroll
            for (int off = 16; off; off >>= 1)
                s += __shfl_xor_sync(0xFFFFFFFFu, s, off);
            if (lane == 0) g_bc[o] = b2[o] + s;
        }
    }
}

// ---------------- kernel 2: Wc = W2 @ W1 (fp16, pure cp.async) -----------
#define WC_A 0
#define WC_B 18432
#define WC_STG 27648

__global__ void __launch_bounds__(256, 2) wc_gemm() {
    extern __shared__ char smn[];
    uint32_t sb = smem_u32(smn);
    const int tid = threadIdx.x, lid = tid & 31, wid = tid >> 5;
    const int wm = wid >> 1, wn = wid & 1, gid = lid >> 2, t4 = lid & 3;
    const int c0 = blockIdx.x * 64;

    const int arow = tid >> 1;
    const int acol = (tid & 1) * 64;
    const char* gA = (const char*)(g_w2f + (size_t)arow * HIDDEN) + acol;
    const uint32_t sA = sb + WC_A + arow * PA + acol;
    const int brow = tid >> 2;
    const int bcol = (tid & 3) * 32;
    const char* gB = (const char*)(g_w1f + (size_t)brow * K_PAD + c0) + bcol;
    const uint32_t sB = sb + WC_B + brow * PA + bcol;

    auto issue = [&](int it, int s) {
        if (it < NCHUNK_WC) {
            uint32_t so = s * WC_STG;
            size_t ka = (size_t)it * 128;
            size_t kb = (size_t)it * 64 * K_PAD * 2;
            #pragma unroll
            for (int i = 0; i < 4; i++) cp16(sA + so + i * 16, gA + ka + i * 16);
            #pragma unroll
            for (int i = 0; i < 2; i++) cp16(sB + so + i * 16, gB + kb + i * 16);
        }
        CP_COMMIT();
    };

    float acc[2][4][4];
    #pragma unroll
    for (int mb = 0; mb < 2; mb++)
        #pragma unroll
        for (int nf = 0; nf < 4; nf++)
            #pragma unroll
            for (int e = 0; e < 4; e++) acc[mb][nf][e] = 0.f;

    issue(0, 0); issue(1, 1); issue(2, 2);
    int sc = 0;
    for (int it = 0; it < NCHUNK_WC; ++it) {
        uint32_t st = sb + sc * WC_STG;
        CP_WAIT2();
        __syncthreads();
        #pragma unroll
        for (int ks = 0; ks < 4; ks++) {
            uint32_t a[2][4];
            #pragma unroll
            for (int mb = 0; mb < 2; mb++) {
                uint32_t r = (wm * 32 + mb * 16 + (lid & 15));
                ldsm4(a[mb], st + WC_A + r * PA + ks * 32 + (lid >> 4) * 16);
            }
            #pragma unroll
            for (int nq = 0; nq < 2; nq++) {
                uint32_t r = ks * 16 + ((lid >> 3) & 1) * 8 + (lid & 7);
                uint32_t cb = (wn * 32 + nq * 16) * 2 + ((lid >> 4) & 1) * 16;
                uint32_t b[4];
                ldsm4t(b, st + WC_B + r * PA + cb);
                #pragma unroll
                for (int mb = 0; mb < 2; mb++)
                    #pragma unroll
                    for (int f = 0; f < 2; f++)
                        mma_f16(acc[mb][nq * 2 + f], a[mb], &b[f * 2]);
            }
        }
        __syncthreads();
        issue(it + 3, sc);
        sc = (sc == 2) ? 0 : sc + 1;
    }

    #pragma unroll
    for (int mb = 0; mb < 2; mb++)
        #pragma unroll
        for (int nf = 0; nf < 4; nf++) {
            int o = wm * 32 + mb * 16 + gid;
            int c = c0 + wn * 32 + nf * 8 + t4 * 2;
            *(__half2*)(g_wcf + (size_t)o * K_PAD + c) =
                __floats2half2_rn(acc[mb][nf][0], acc[mb][nf][1]);
            *(__half2*)(g_wcf + (size_t)(o + 8) * K_PAD + c) =
                __floats2half2_rn(acc[mb][nf][2], acc[mb][nf][3]);
        }
}

// ---------------- kernel 3: main GEMM  part = hist @ Wc^T (fp16) ---------
// CTA: 128 m x 128 n, K-slice 1280 (20 chunks). grid (32, 8). 8 warps.
// 3-stage cp.async; LDSM fragments double-buffered across ks to break the
// LDSM->MMA RAW chain (the round-7 stall signature).
#define MG_A    0                      // 3 x 18432
#define MG_B    55296                  // 3 x 18432
#define MG_SMEM 110592

__global__ void __launch_bounds__(256, 2) main_gemm() {
    extern __shared__ char smn[];
    uint32_t sb = smem_u32(smn);
    const int tid = threadIdx.x, lid = tid & 31, wid = tid >> 5;
    const int wm = wid >> 1, wn = wid & 1, gid = lid >> 2, t4 = lid & 3;
    const int m0 = blockIdx.x * 128;
    const int kbase = blockIdx.y * K_SLICE;

    const int row = tid >> 1;
    const int hf  = tid & 1;
    const char* gA = (const char*)(g_hist + (size_t)(m0 + row) * K_PAD + kbase) + hf * 64;
    const char* gB = (const char*)(g_wcf  + (size_t)row * K_PAD + kbase) + hf * 64;
    const uint32_t sA = sb + MG_A + row * PA + hf * 64;
    const uint32_t sB = sb + MG_B + row * PA + hf * 64;

    auto issue = [&](int it, int s) {
        if (it < NCHUNK_MAIN) {
            size_t ko = (size_t)it * 128;
            uint32_t so = s * 18432;
            #pragma unroll
            for (int i = 0; i < 4; i++) {
                cp16(sA + so + i * 16, gA + ko + i * 16);
                cp16(sB + so + i * 16, gB + ko + i * 16);
            }
        }
        CP_COMMIT();
    };

    float acc[2][8][4];
    #pragma unroll
    for (int mb = 0; mb < 2; mb++)
        #pragma unroll
        for (int nf = 0; nf < 8; nf++)
            #pragma unroll
            for (int e = 0; e < 4; e++) acc[mb][nf][e] = 0.f;

    // per-thread ldmatrix source addresses (ks-invariant parts)
    const uint32_t arow_a0 = (wm * 32 + (lid & 15)) * PA + (lid >> 4) * 16;
    const uint32_t arow_a1 = arow_a0 + 16 * PA;
    const uint32_t brow_b  = (wn * 64 + ((lid >> 4) & 1) * 8 + (lid & 7)) * PA
                             + ((lid >> 3) & 1) * 16;

    issue(0, 0); issue(1, 1); issue(2, 2);
    int sc = 0;
    for (int it = 0; it < NCHUNK_MAIN; ++it) {
        CP_WAIT2();
        __syncthreads();
        uint32_t stA = sb + MG_A + sc * 18432;
        uint32_t stB = sb + MG_B + sc * 18432;

        uint32_t af[2][2][4], bf[2][4][4];
        auto ldf = [&](int ks, int buf) {
            uint32_t ko = ks * 32;
            ldsm4(af[buf][0], stA + arow_a0 + ko);
            ldsm4(af[buf][1], stA + arow_a1 + ko);
            #pragma unroll
            for (int nq = 0; nq < 4; nq++)
                ldsm4(bf[buf][nq], stB + brow_b + nq * 16 * PA + ko);
        };

        ldf(0, 0);
        #pragma unroll
        for (int ks = 0; ks < 4; ks++) {
            int cur = ks & 1;
            if (ks < 3) ldf(ks + 1, cur ^ 1);
            #pragma unroll
            for (int nq = 0; nq < 4; nq++)
                #pragma unroll
                for (int mb = 0; mb < 2; mb++)
                    #pragma unroll
                    for (int f = 0; f < 2; f++)
                        mma_f16(acc[mb][nq * 2 + f], af[cur][mb],
                                &bf[cur][nq][f * 2]);
        }
        __syncthreads();
        issue(it + 3, sc);
        sc = (sc == 2) ? 0 : sc + 1;
    }

    float* base = g_part + (size_t)blockIdx.y * BATCH * PPITCH;
    #pragma unroll
    for (int mb = 0; mb < 2; mb++)
        #pragma unroll
        for (int nf = 0; nf < 8; nf++) {
            int r = m0 + wm * 32 + mb * 16 + gid;
            int c = wn * 64 + nf * 8 + t4 * 2;
            if (c < OUTPUT) {
                *(float2*)(base + (size_t)r * PPITCH + c) =
                    make_float2(acc[mb][nf][0], acc[mb][nf][1]);
                *(float2*)(base + (size_t)(r + 8) * PPITCH + c) =
                    make_float2(acc[mb][nf][2], acc[mb][nf][3]);
            }
        }
}

// ---------------- kernel 4: split-K reduce + bias ------------------------
__global__ void __launch_bounds__(256) reduce_kernel(float* __restrict__ out) {
    int i = blockIdx.x * 256 + threadIdx.x;
    int b = i / OUTPUT;
    int o = i - b * OUTPUT;
    float s = g_bc[o];
    #pragma unroll
    for (int sl = 0; sl < NSLICE; sl++)
        s += g_part[((size_t)sl * BATCH + b) * PPITCH + o];
    out[i] = s;
}

// ---------------- launch ---------------------------------------------------
extern "C" void kernel_launch(void* const* d_in, const int* in_sizes, int n_in,
                              void* d_out, int out_size) {
    const int*   words = (const int*)  d_in[0];
    const float* W1    = (const float*)d_in[1];
    const float* b1    = (const float*)d_in[2];
    const float* W2    = (const float*)d_in[3];
    const float* b2    = (const float*)d_in[4];

    static cudaStream_t s2 = nullptr;
    static cudaEvent_t ev_fork = nullptr, ev_join = nullptr;
    if (s2 == nullptr) {
        cudaStreamCreateWithFlags(&s2, cudaStreamNonBlocking);
        cudaEventCreateWithFlags(&ev_fork, cudaEventDisableTiming);
        cudaEventCreateWithFlags(&ev_join, cudaEventDisableTiming);
        cudaFuncSetAttribute(wc_gemm,
            cudaFuncAttributeMaxDynamicSharedMemorySize, 3 * WC_STG);
        cudaFuncSetAttribute(main_gemm,
            cudaFuncAttributeMaxDynamicSharedMemorySize, MG_SMEM);
    }

    cudaEventRecord(ev_fork, 0);
    cudaStreamWaitEvent(s2, ev_fork, 0);

    hist_kernel<<<BATCH, 256, 0, 0>>>(words);

    conv_kernel<<<NB_CONV, 256, 0, s2>>>(W1, b1, W2, b2);
    wc_gemm<<<K_PAD / 64, 256, 3 * WC_STG, s2>>>();
    cudaEventRecord(ev_join, s2);

    cudaStreamWaitEvent(0, ev_join, 0);

    main_gemm<<<dim3(32, NSLICE), 256, MG_SMEM, 0>>>();
    reduce_kernel<<<(BATCH * OUTPUT) / 256, 256, 0, 0>>>((float*)d_out);
}

// round 9
// speedup vs baseline: 1.0402x; 1.0402x over previous
#include <cuda_runtime.h>
#include <cuda_fp16.h>
#include <cstdint>

#define CHARS   10000
#define HIDDEN  1024
#define OUTPUT  100
#define BATCH   4096
#define MAXLEN  2048

#define K_PAD   10240
#define NPAD    128
#define PPITCH  104                   // g_part row pitch (floats)
#define NSLICE  8
#define K_SLICE (K_PAD / NSLICE)      // 1280
#define NCHUNK_MAIN (K_SLICE / 64)    // 20
#define NCHUNK_WC   (HIDDEN / 64)     // 16

// ---------------- device scratch (static; allocations are banned) --------
__device__ __half  g_hist[(size_t)BATCH * K_PAD];           // 84 MB
__device__ __half  g_w1f[(size_t)HIDDEN * K_PAD];           // 21 MB
__device__ __half  g_w2f[(size_t)NPAD * HIDDEN];            // 256 KB
__device__ __half  g_wcf[(size_t)NPAD * K_PAD];             // 2.6 MB
__device__ float   g_part[(size_t)NSLICE * BATCH * PPITCH]; // 13.6 MB
__device__ float   g_bc[OUTPUT];

// ---------------- PTX helpers (portable sm_80-class only) ----------------
__device__ __forceinline__ uint32_t smem_u32(const void* p) {
    uint32_t a;
    asm("{ .reg .u64 t; cvta.to.shared.u64 t, %1; cvt.u32.u64 %0, t; }"
        : "=r"(a) : "l"(p));
    return a;
}

__device__ __forceinline__ void cp16(uint32_t s, const void* g) {
    asm volatile("cp.async.cg.shared.global [%0], [%1], 16;" :: "r"(s), "l"(g));
}
#define CP_COMMIT() asm volatile("cp.async.commit_group;" ::: "memory")
#define CP_WAIT1()  asm volatile("cp.async.wait_group 1;"  ::: "memory")

__device__ __forceinline__ void ldsm4(uint32_t* r, uint32_t a) {
    asm volatile("ldmatrix.sync.aligned.m8n8.x4.shared.b16 {%0,%1,%2,%3}, [%4];"
        : "=r"(r[0]), "=r"(r[1]), "=r"(r[2]), "=r"(r[3]) : "r"(a));
}
__device__ __forceinline__ void ldsm4t(uint32_t* r, uint32_t a) {
    asm volatile("ldmatrix.sync.aligned.m8n8.x4.trans.shared.b16 {%0,%1,%2,%3}, [%4];"
        : "=r"(r[0]), "=r"(r[1]), "=r"(r[2]), "=r"(r[3]) : "r"(a));
}

// D(16x8,f32) += A(16x16,f16) @ B(16x8,f16)
__device__ __forceinline__ void mma_f16(float* c, const uint32_t* a, const uint32_t* b) {
    asm volatile(
        "mma.sync.aligned.m16n8k16.row.col.f32.f16.f16.f32 "
        "{%0,%1,%2,%3}, {%4,%5,%6,%7}, {%8,%9}, {%0,%1,%2,%3};"
        : "+f"(c[0]), "+f"(c[1]), "+f"(c[2]), "+f"(c[3])
        : "r"(a[0]), "r"(a[1]), "r"(a[2]), "r"(a[3]), "r"(b[0]), "r"(b[1]));
}

// smem pitch (bytes) for 64-col 16-bit rows, +8 elem pad
#define PA 144

// ---------------- kernel 1: fused prelude ---------------------------------
// [0,4096): per-row histogram -> fp16
// [4096,5120): W1 row -> fp16 (padded); [5120,5632): W2 -> fp16; [5632,5645): bc
#define NB_HIST 4096
#define NB_W1   1024
#define NB_W2   512
#define NB_BC   13
#define NB_TOTAL (NB_HIST + NB_W1 + NB_W2 + NB_BC)

__global__ void __launch_bounds__(256) prelude_kernel(
        const int* __restrict__ words, const float* __restrict__ W1,
        const float* __restrict__ b1,  const float* __restrict__ W2,
        const float* __restrict__ b2) {
    __shared__ unsigned cnt[K_PAD / 2];
    const int bid = blockIdx.x, tid = threadIdx.x;

    if (bid < NB_HIST) {
        for (int i = tid; i < K_PAD / 2; i += 256) cnt[i] = 0u;
        __syncthreads();
        const int* w = words + (size_t)bid * MAXLEN;
        #pragma unroll 8
        for (int j = tid; j < MAXLEN; j += 256) {
            unsigned c = (unsigned)w[j];
            atomicAdd(&cnt[c >> 1], 1u << ((c & 1u) * 16));
        }
        __syncthreads();
        __half2* out = (__half2*)(g_hist + (size_t)bid * K_PAD);
        for (int i = tid; i < K_PAD / 2; i += 256) {
            unsigned v = cnt[i];
            out[i] = __floats2half2_rn((float)(v & 0xFFFFu), (float)(v >> 16));
        }
    } else if (bid < NB_HIST + NB_W1) {
        int h = bid - NB_HIST;
        const float* src = W1 + (size_t)h * CHARS;
        __half2* dst = (__half2*)(g_w1f + (size_t)h * K_PAD);
        for (int i = tid; i < K_PAD / 2; i += 256) {
            float2 v = (i < CHARS / 2) ? *(const float2*)(src + 2 * i)
                                       : make_float2(0.f, 0.f);
            dst[i] = __floats2half2_rn(v.x, v.y);
        }
    } else if (bid < NB_HIST + NB_W1 + NB_W2) {
        unsigned i = (bid - NB_HIST - NB_W1) * 256u + tid;   // over 128*1024
        unsigned o = i >> 10;
        float v = (o < OUTPUT) ? W2[(size_t)o * HIDDEN + (i & 1023u)] : 0.f;
        g_w2f[i] = __float2half_rn(v);
    } else {
        int o = (bid - NB_HIST - NB_W1 - NB_W2) * 8 + (tid >> 5);
        if (o < OUTPUT) {
            int lane = tid & 31;
            const float* w = W2 + (size_t)o * HIDDEN;
            float s = 0.f;
            #pragma unroll 8
            for (int h = lane; h < HIDDEN; h += 32) s += w[h] * b1[h];
            #pragma unroll
            for (int off = 16; off; off >>= 1)
                s += __shfl_xor_sync(0xFFFFFFFFu, s, off);
            if (lane == 0) g_bc[o] = b2[o] + s;
        }
    }
}

// ---------------- kernel 2: Wc = W2 @ W1 (fp16, one barrier/iter) --------
#define WC_A 0
#define WC_B 18432
#define WC_STG 27648

__global__ void __launch_bounds__(256, 2) wc_gemm() {
    extern __shared__ char smn[];
    uint32_t sb = smem_u32(smn);
    const int tid = threadIdx.x, lid = tid & 31, wid = tid >> 5;
    const int wm = wid >> 1, wn = wid & 1, gid = lid >> 2, t4 = lid & 3;
    const int c0 = blockIdx.x * 64;

    const int arow = tid >> 1;
    const int acol = (tid & 1) * 64;
    const char* gA = (const char*)(g_w2f + (size_t)arow * HIDDEN) + acol;
    const uint32_t sA = sb + WC_A + arow * PA + acol;
    const int brow = tid >> 2;
    const int bcol = (tid & 3) * 32;
    const char* gB = (const char*)(g_w1f + (size_t)brow * K_PAD + c0) + bcol;
    const uint32_t sB = sb + WC_B + brow * PA + bcol;

    auto issue = [&](int it, int s) {
        if (it < NCHUNK_WC) {
            uint32_t so = s * WC_STG;
            size_t ka = (size_t)it * 128;
            size_t kb = (size_t)it * 64 * K_PAD * 2;
            #pragma unroll
            for (int i = 0; i < 4; i++) cp16(sA + so + i * 16, gA + ka + i * 16);
            #pragma unroll
            for (int i = 0; i < 2; i++) cp16(sB + so + i * 16, gB + kb + i * 16);
        }
        CP_COMMIT();
    };

    float acc[2][4][4];
    #pragma unroll
    for (int mb = 0; mb < 2; mb++)
        #pragma unroll
        for (int nf = 0; nf < 4; nf++)
            #pragma unroll
            for (int e = 0; e < 4; e++) acc[mb][nf][e] = 0.f;

    issue(0, 0); issue(1, 1);
    int sc = 0, sn = 2;
    for (int it = 0; it < NCHUNK_WC; ++it) {
        uint32_t st = sb + sc * WC_STG;
        CP_WAIT1();
        __syncthreads();               // chunk it ready; slot sn free (read it-1)
        issue(it + 2, sn);
        #pragma unroll
        for (int ks = 0; ks < 4; ks++) {
            uint32_t a[2][4];
            #pragma unroll
            for (int mb = 0; mb < 2; mb++) {
                uint32_t r = (wm * 32 + mb * 16 + (lid & 15));
                ldsm4(a[mb], st + WC_A + r * PA + ks * 32 + (lid >> 4) * 16);
            }
            #pragma unroll
            for (int nq = 0; nq < 2; nq++) {
                uint32_t r = ks * 16 + ((lid >> 3) & 1) * 8 + (lid & 7);
                uint32_t cb = (wn * 32 + nq * 16) * 2 + ((lid >> 4) & 1) * 16;
                uint32_t b[4];
                ldsm4t(b, st + WC_B + r * PA + cb);
                #pragma unroll
                for (int mb = 0; mb < 2; mb++)
                    #pragma unroll
                    for (int f = 0; f < 2; f++)
                        mma_f16(acc[mb][nq * 2 + f], a[mb], &b[f * 2]);
            }
        }
        sc = (sc == 2) ? 0 : sc + 1;
        sn = (sn == 2) ? 0 : sn + 1;
    }

    #pragma unroll
    for (int mb = 0; mb < 2; mb++)
        #pragma unroll
        for (int nf = 0; nf < 4; nf++) {
            int o = wm * 32 + mb * 16 + gid;
            int c = c0 + wn * 32 + nf * 8 + t4 * 2;
            *(__half2*)(g_wcf + (size_t)o * K_PAD + c) =
                __floats2half2_rn(acc[mb][nf][0], acc[mb][nf][1]);
            *(__half2*)(g_wcf + (size_t)(o + 8) * K_PAD + c) =
                __floats2half2_rn(acc[mb][nf][2], acc[mb][nf][3]);
        }
}

// ---------------- kernel 3: main GEMM  part = hist @ Wc^T (fp16) ---------
// CTA: 128 m x 128 n, K-slice 1280 (20 chunks). grid (32, 8). 8 warps.
// 3 smem stages, ONE __syncthreads per iteration (issue it+2 post-barrier).
#define MG_A    0                      // 3 x 18432
#define MG_B    55296                  // 3 x 18432
#define MG_SMEM 110592

__global__ void __launch_bounds__(256, 2) main_gemm() {
    extern __shared__ char smn[];
    uint32_t sb = smem_u32(smn);
    const int tid = threadIdx.x, lid = tid & 31, wid = tid >> 5;
    const int wm = wid >> 1, wn = wid & 1, gid = lid >> 2, t4 = lid & 3;
    const int m0 = blockIdx.x * 128;
    const int kbase = blockIdx.y * K_SLICE;

    const int row = tid >> 1;
    const int hf  = tid & 1;
    const char* gA = (const char*)(g_hist + (size_t)(m0 + row) * K_PAD + kbase) + hf * 64;
    const char* gB = (const char*)(g_wcf  + (size_t)row * K_PAD + kbase) + hf * 64;
    const uint32_t sA = sb + MG_A + row * PA + hf * 64;
    const uint32_t sB = sb + MG_B + row * PA + hf * 64;

    auto issue = [&](int it, int s) {
        if (it < NCHUNK_MAIN) {
            size_t ko = (size_t)it * 128;
            uint32_t so = s * 18432;
            #pragma unroll
            for (int i = 0; i < 4; i++) {
                cp16(sA + so + i * 16, gA + ko + i * 16);
                cp16(sB + so + i * 16, gB + ko + i * 16);
            }
        }
        CP_COMMIT();
    };

    float acc[2][8][4];
    #pragma unroll
    for (int mb = 0; mb < 2; mb++)
        #pragma unroll
        for (int nf = 0; nf < 8; nf++)
            #pragma unroll
            for (int e = 0; e < 4; e++) acc[mb][nf][e] = 0.f;

    const uint32_t aoff0 = (wm * 32 + (lid & 15)) * PA + (lid >> 4) * 16;
    const uint32_t aoff1 = aoff0 + 16 * PA;
    const uint32_t boff  = (wn * 64 + ((lid >> 4) & 1) * 8 + (lid & 7)) * PA
                           + ((lid >> 3) & 1) * 16;

    issue(0, 0); issue(1, 1);
    int sc = 0, sn = 2;
    for (int it = 0; it < NCHUNK_MAIN; ++it) {
        uint32_t stA = sb + MG_A + sc * 18432;
        uint32_t stB = sb + MG_B + sc * 18432;
        CP_WAIT1();
        __syncthreads();               // chunk it ready; slot sn free
        issue(it + 2, sn);
        #pragma unroll
        for (int ks = 0; ks < 4; ks++) {
            uint32_t ko = ks * 32;
            uint32_t a[2][4], b[4][4];
            ldsm4(a[0], stA + aoff0 + ko);
            ldsm4(a[1], stA + aoff1 + ko);
            #pragma unroll
            for (int nq = 0; nq < 4; nq++)
                ldsm4(b[nq], stB + boff + nq * 16 * PA + ko);
            #pragma unroll
            for (int nq = 0; nq < 4; nq++)
                #pragma unroll
                for (int mb = 0; mb < 2; mb++)
                    #pragma unroll
                    for (int f = 0; f < 2; f++)
                        mma_f16(acc[mb][nq * 2 + f], a[mb], &b[nq][f * 2]);
        }
        sc = (sc == 2) ? 0 : sc + 1;
        sn = (sn == 2) ? 0 : sn + 1;
    }

    float* base = g_part + (size_t)blockIdx.y * BATCH * PPITCH;
    #pragma unroll
    for (int mb = 0; mb < 2; mb++)
        #pragma unroll
        for (int nf = 0; nf < 8; nf++) {
            int r = m0 + wm * 32 + mb * 16 + gid;
            int c = wn * 64 + nf * 8 + t4 * 2;
            if (c < OUTPUT) {
                *(float2*)(base + (size_t)r * PPITCH + c) =
                    make_float2(acc[mb][nf][0], acc[mb][nf][1]);
                *(float2*)(base + (size_t)(r + 8) * PPITCH + c) =
                    make_float2(acc[mb][nf][2], acc[mb][nf][3]);
            }
        }
}

// ---------------- kernel 4: split-K reduce + bias (float4) ---------------
// one thread per 4 outputs: BATCH*25 threads, 400 blocks.
__global__ void __launch_bounds__(256) reduce_kernel(float* __restrict__ out) {
    int i = blockIdx.x * 256 + threadIdx.x;       // over BATCH*25
    int b = i / 25;
    int o = (i - b * 25) * 4;
    float4 s = *(const float4*)(g_bc + o);
    #pragma unroll
    for (int sl = 0; sl < NSLICE; sl++) {
        float4 p = *(const float4*)(g_part + ((size_t)sl * BATCH + b) * PPITCH + o);
        s.x += p.x; s.y += p.y; s.z += p.z; s.w += p.w;
    }
    *(float4*)(out + (size_t)b * OUTPUT + o) = s;
}

// ---------------- launch ---------------------------------------------------
extern "C" void kernel_launch(void* const* d_in, const int* in_sizes, int n_in,
                              void* d_out, int out_size) {
    const int*   words = (const int*)  d_in[0];
    const float* W1    = (const float*)d_in[1];
    const float* b1    = (const float*)d_in[2];
    const float* W2    = (const float*)d_in[3];
    const float* b2    = (const float*)d_in[4];

    cudaFuncSetAttribute(wc_gemm,
        cudaFuncAttributeMaxDynamicSharedMemorySize, 3 * WC_STG);
    cudaFuncSetAttribute(main_gemm,
        cudaFuncAttributeMaxDynamicSharedMemorySize, MG_SMEM);

    prelude_kernel<<<NB_TOTAL, 256>>>(words, W1, b1, W2, b2);
    wc_gemm<<<K_PAD / 64, 256, 3 * WC_STG>>>();
    main_gemm<<<dim3(32, NSLICE), 256, MG_SMEM>>>();
    reduce_kernel<<<(BATCH * 25) / 256, 256>>>((float*)d_out);
}

// round 10
// speedup vs baseline: 1.0504x; 1.0098x over previous
#include <cuda_runtime.h>
#include <cuda_fp16.h>
#include <cstdint>

#define CHARS   10000
#define HIDDEN  1024
#define OUTPUT  100
#define BATCH   4096
#define MAXLEN  2048

#define K_PAD   10240
#define NPAD    128
#define PPITCH  104
#define NSLICE  8
#define K_SLICE (K_PAD / NSLICE)      // 1280
#define NCHUNK_MAIN (K_SLICE / 64)    // 20
#define NCHUNK_WC   (HIDDEN / 64)     // 16

// ---------------- device scratch (static; allocations are banned) --------
__device__ __half  g_hist[(size_t)BATCH * K_PAD];           // 84 MB
__device__ __half  g_w2f[(size_t)NPAD * HIDDEN];            // 256 KB
__device__ __half  g_wcf[(size_t)NPAD * K_PAD];             // 2.6 MB
__device__ float   g_part[(size_t)NSLICE * BATCH * PPITCH]; // 13.6 MB
__device__ float   g_bc[OUTPUT];

// ---------------- PTX helpers (portable sm_80-class only) ----------------
__device__ __forceinline__ uint32_t smem_u32(const void* p) {
    uint32_t a;
    asm("{ .reg .u64 t; cvta.to.shared.u64 t, %1; cvt.u32.u64 %0, t; }"
        : "=r"(a) : "l"(p));
    return a;
}

__device__ __forceinline__ void cp16(uint32_t s, const void* g) {
    asm volatile("cp.async.cg.shared.global [%0], [%1], 16;" :: "r"(s), "l"(g));
}
#define CP_COMMIT() asm volatile("cp.async.commit_group;" ::: "memory")
#define CP_WAIT1()  asm volatile("cp.async.wait_group 1;"  ::: "memory")

__device__ __forceinline__ void ldsm4(uint32_t* r, uint32_t a) {
    asm volatile("ldmatrix.sync.aligned.m8n8.x4.shared.b16 {%0,%1,%2,%3}, [%4];"
        : "=r"(r[0]), "=r"(r[1]), "=r"(r[2]), "=r"(r[3]) : "r"(a));
}
__device__ __forceinline__ void ldsm4t(uint32_t* r, uint32_t a) {
    asm volatile("ldmatrix.sync.aligned.m8n8.x4.trans.shared.b16 {%0,%1,%2,%3}, [%4];"
        : "=r"(r[0]), "=r"(r[1]), "=r"(r[2]), "=r"(r[3]) : "r"(a));
}

// D(16x8,f32) += A(16x16,f16) @ B(16x8,f16)
__device__ __forceinline__ void mma_f16(float* c, const uint32_t* a, const uint32_t* b) {
    asm volatile(
        "mma.sync.aligned.m16n8k16.row.col.f32.f16.f16.f32 "
        "{%0,%1,%2,%3}, {%4,%5,%6,%7}, {%8,%9}, {%0,%1,%2,%3};"
        : "+f"(c[0]), "+f"(c[1]), "+f"(c[2]), "+f"(c[3])
        : "r"(a[0]), "r"(a[1]), "r"(a[2]), "r"(a[3]), "r"(b[0]), "r"(b[1]));
}

#define PA 144     // smem pitch (bytes) for 64-col 16-bit rows, +8 elem pad

// ---------------- kernel 1: prelude (hist + W2 conv + bc) ----------------
#define NB_HIST 4096
#define NB_W2   512
#define NB_BC   13
#define NB_TOTAL (NB_HIST + NB_W2 + NB_BC)

__global__ void __launch_bounds__(256) prelude_kernel(
        const int* __restrict__ words, const float* __restrict__ b1,
        const float* __restrict__ W2,  const float* __restrict__ b2) {
    __shared__ unsigned cnt[K_PAD / 2];
    const int bid = blockIdx.x, tid = threadIdx.x;

    if (bid < NB_HIST) {
        for (int i = tid; i < K_PAD / 2; i += 256) cnt[i] = 0u;
        __syncthreads();
        const int* w = words + (size_t)bid * MAXLEN;
        #pragma unroll 8
        for (int j = tid; j < MAXLEN; j += 256) {
            unsigned c = (unsigned)w[j];
            atomicAdd(&cnt[c >> 1], 1u << ((c & 1u) * 16));
        }
        __syncthreads();
        __half2* out = (__half2*)(g_hist + (size_t)bid * K_PAD);
        for (int i = tid; i < K_PAD / 2; i += 256) {
            unsigned v = cnt[i];
            out[i] = __floats2half2_rn((float)(v & 0xFFFFu), (float)(v >> 16));
        }
    } else if (bid < NB_HIST + NB_W2) {
        unsigned i = (bid - NB_HIST) * 256u + tid;           // over 128*1024
        unsigned o = i >> 10;
        float v = (o < OUTPUT) ? W2[(size_t)o * HIDDEN + (i & 1023u)] : 0.f;
        g_w2f[i] = __float2half_rn(v);
    } else {
        int o = (bid - NB_HIST - NB_W2) * 8 + (tid >> 5);
        if (o < OUTPUT) {
            int lane = tid & 31;
            const float* w = W2 + (size_t)o * HIDDEN;
            float s = 0.f;
            #pragma unroll 8
            for (int h = lane; h < HIDDEN; h += 32) s += w[h] * b1[h];
            #pragma unroll
            for (int off = 16; off; off >>= 1)
                s += __shfl_xor_sync(0xFFFFFFFFu, s, off);
            if (lane == 0) g_bc[o] = b2[o] + s;
        }
    }
}

// ---------------- kernel 2: Wc = W2 @ W1 (fused W1 fp32->fp16) -----------
// CTA 128 o x 64 c, K=1024 (16 chunks). grid 160. 8 warps (4m x 2n).
// A = W2 fp16 cp.async (3 stages); B = W1 fp32 LDG -> cvt -> STS (3 B slots,
// written one chunk ahead). One barrier per iteration.
#define WC_A 0
#define WC_B 18432
#define WC_STG 27648

__global__ void __launch_bounds__(256, 2) wc_gemm(const float* __restrict__ W1) {
    extern __shared__ char smn[];
    uint32_t sb = smem_u32(smn);
    const int tid = threadIdx.x, lid = tid & 31, wid = tid >> 5;
    const int wm = wid >> 1, wn = wid & 1, gid = lid >> 2, t4 = lid & 3;
    const int c0 = blockIdx.x * 64;

    // A (W2 fp16): 128 o-rows x 128B per chunk
    const int arow = tid >> 1;
    const int acol = (tid & 1) * 64;
    const char* gA = (const char*)(g_w2f + (size_t)arow * HIDDEN) + acol;
    const uint32_t sA = sb + WC_A + arow * PA + acol;

    // B (W1 fp32): 64 h-rows x 64 c per chunk; thread: row=tid>>2, 16 floats
    const int brow = tid >> 2;
    const int bcole = (tid & 3) * 16;
    const uint32_t oB = WC_B + brow * PA + bcole * 2;

    float4 rb[4];
    auto loadB = [&](int it) {
        const float* p = W1 + (size_t)(it * 64 + brow) * CHARS + c0 + bcole;
        #pragma unroll
        for (int i = 0; i < 4; i++) {
            int c = c0 + bcole + i * 4;
            rb[i] = (c < CHARS) ? *(const float4*)(p + i * 4)
                                : make_float4(0.f, 0.f, 0.f, 0.f);
        }
    };
    auto stsB = [&](int slot) {
        uint32_t so = slot * WC_STG;
        #pragma unroll
        for (int j = 0; j < 2; j++) {
            __half2 h0 = __floats2half2_rn(rb[2*j].x,   rb[2*j].y);
            __half2 h1 = __floats2half2_rn(rb[2*j].z,   rb[2*j].w);
            __half2 h2 = __floats2half2_rn(rb[2*j+1].x, rb[2*j+1].y);
            __half2 h3 = __floats2half2_rn(rb[2*j+1].z, rb[2*j+1].w);
            *(uint4*)(smn + oB + so + j * 16) =
                make_uint4(*(uint32_t*)&h0, *(uint32_t*)&h1,
                           *(uint32_t*)&h2, *(uint32_t*)&h3);
        }
    };
    auto cpA = [&](int it, int slot) {
        if (it < NCHUNK_WC) {
            uint32_t so = slot * WC_STG;
            size_t ka = (size_t)it * 128;
            #pragma unroll
            for (int i = 0; i < 4; i++) cp16(sA + so + i * 16, gA + ka + i * 16);
        }
        CP_COMMIT();
    };

    float acc[2][4][4];
    #pragma unroll
    for (int mb = 0; mb < 2; mb++)
        #pragma unroll
        for (int nf = 0; nf < 4; nf++)
            #pragma unroll
            for (int e = 0; e < 4; e++) acc[mb][nf][e] = 0.f;

    // prologue: B(0) stored; B(1) in regs; A(0),A(1) in flight
    loadB(0); stsB(0);
    loadB(1);
    cpA(0, 0); cpA(1, 1);

    int sc = 0, sn = 2;
    for (int it = 0; it < NCHUNK_WC; ++it) {
        uint32_t st = sb + sc * WC_STG;
        CP_WAIT1();
        __syncthreads();                 // A(it) + stsB(it) visible; slot sn free
        if (it + 1 < NCHUNK_WC) stsB((it + 1) % 3);   // rb holds chunk it+1
        if (it + 2 < NCHUNK_WC) loadB(it + 2);
        cpA(it + 2, sn);
        #pragma unroll
        for (int ks = 0; ks < 4; ks++) {
            uint32_t a[2][4];
            #pragma unroll
            for (int mb = 0; mb < 2; mb++) {
                uint32_t r = (wm * 32 + mb * 16 + (lid & 15));
                ldsm4(a[mb], st + WC_A + r * PA + ks * 32 + (lid >> 4) * 16);
            }
            #pragma unroll
            for (int nq = 0; nq < 2; nq++) {
                uint32_t r = ks * 16 + ((lid >> 3) & 1) * 8 + (lid & 7);
                uint32_t cb = (wn * 32 + nq * 16) * 2 + ((lid >> 4) & 1) * 16;
                uint32_t b[4];
                ldsm4t(b, st + WC_B + r * PA + cb);
                #pragma unroll
                for (int mb = 0; mb < 2; mb++)
                    #pragma unroll
                    for (int f = 0; f < 2; f++)
                        mma_f16(acc[mb][nq * 2 + f], a[mb], &b[f * 2]);
            }
        }
        sc = (sc == 2) ? 0 : sc + 1;
        sn = (sn == 2) ? 0 : sn + 1;
    }

    #pragma unroll
    for (int mb = 0; mb < 2; mb++)
        #pragma unroll
        for (int nf = 0; nf < 4; nf++) {
            int o = wm * 32 + mb * 16 + gid;
            int c = c0 + wn * 32 + nf * 8 + t4 * 2;
            *(__half2*)(g_wcf + (size_t)o * K_PAD + c) =
                __floats2half2_rn(acc[mb][nf][0], acc[mb][nf][1]);
            *(__half2*)(g_wcf + (size_t)(o + 8) * K_PAD + c) =
                __floats2half2_rn(acc[mb][nf][2], acc[mb][nf][3]);
        }
}

// ---------------- kernel 3: main GEMM  part = hist @ Wc^T (fp16) ---------
// CTA 128 m x 128 n, 128 threads = 4 warps of 64x64 (2m x 2n) -> halves
// ldmatrix bytes per MMA (the R9 bottleneck). 3 stages, one barrier/iter.
#define MG_A    0                      // 3 x 18432
#define MG_B    55296                  // 3 x 18432
#define MG_SMEM 110592

__global__ void __launch_bounds__(128, 2) main_gemm() {
    extern __shared__ char smn[];
    uint32_t sb = smem_u32(smn);
    const int tid = threadIdx.x, lid = tid & 31, wid = tid >> 5;
    const int wm = wid >> 1, wn = wid & 1, gid = lid >> 2, t4 = lid & 3;
    const int m0 = blockIdx.x * 128;
    const int kbase = blockIdx.y * K_SLICE;

    // cp.async: 128 threads, one 128B row each per operand per chunk
    const char* gA = (const char*)(g_hist + (size_t)(m0 + tid) * K_PAD + kbase);
    const char* gB = (const char*)(g_wcf  + (size_t)tid * K_PAD + kbase);
    const uint32_t sA = sb + MG_A + tid * PA;
    const uint32_t sB = sb + MG_B + tid * PA;

    auto issue = [&](int it, int s) {
        if (it < NCHUNK_MAIN) {
            size_t ko = (size_t)it * 128;
            uint32_t so = s * 18432;
            #pragma unroll
            for (int i = 0; i < 8; i++) {
                cp16(sA + so + i * 16, gA + ko + i * 16);
                cp16(sB + so + i * 16, gB + ko + i * 16);
            }
        }
        CP_COMMIT();
    };

    float acc[4][8][4];
    #pragma unroll
    for (int mb = 0; mb < 4; mb++)
        #pragma unroll
        for (int nf = 0; nf < 8; nf++)
            #pragma unroll
            for (int e = 0; e < 4; e++) acc[mb][nf][e] = 0.f;

    const uint32_t aoff = (wm * 64 + (lid & 15)) * PA + (lid >> 4) * 16;
    const uint32_t boff = (wn * 64 + ((lid >> 4) & 1) * 8 + (lid & 7)) * PA
                          + ((lid >> 3) & 1) * 16;

    issue(0, 0); issue(1, 1);
    int sc = 0, sn = 2;
    for (int it = 0; it < NCHUNK_MAIN; ++it) {
        uint32_t stA = sb + MG_A + sc * 18432;
        uint32_t stB = sb + MG_B + sc * 18432;
        CP_WAIT1();
        __syncthreads();
        issue(it + 2, sn);
        #pragma unroll
        for (int ks = 0; ks < 4; ks++) {
            uint32_t ko = ks * 32;
            uint32_t a[4][4], b[4][4];
            #pragma unroll
            for (int mb = 0; mb < 4; mb++)
                ldsm4(a[mb], stA + aoff + mb * 16 * PA + ko);
            #pragma unroll
            for (int nq = 0; nq < 4; nq++)
                ldsm4(b[nq], stB + boff + nq * 16 * PA + ko);
            #pragma unroll
            for (int nq = 0; nq < 4; nq++)
                #pragma unroll
                for (int mb = 0; mb < 4; mb++)
                    #pragma unroll
                    for (int f = 0; f < 2; f++)
                        mma_f16(acc[mb][nq * 2 + f], a[mb], &b[nq][f * 2]);
        }
        sc = (sc == 2) ? 0 : sc + 1;
        sn = (sn == 2) ? 0 : sn + 1;
    }

    float* base = g_part + (size_t)blockIdx.y * BATCH * PPITCH;
    #pragma unroll
    for (int mb = 0; mb < 4; mb++)
        #pragma unroll
        for (int nf = 0; nf < 8; nf++) {
            int r = m0 + wm * 64 + mb * 16 + gid;
            int c = wn * 64 + nf * 8 + t4 * 2;
            if (c < OUTPUT) {
                *(float2*)(base + (size_t)r * PPITCH + c) =
                    make_float2(acc[mb][nf][0], acc[mb][nf][1]);
                *(float2*)(base + (size_t)(r + 8) * PPITCH + c) =
                    make_float2(acc[mb][nf][2], acc[mb][nf][3]);
            }
        }
}

// ---------------- kernel 4: split-K reduce + bias (float4) ---------------
__global__ void __launch_bounds__(256) reduce_kernel(float* __restrict__ out) {
    int i = blockIdx.x * 256 + threadIdx.x;       // over BATCH*25
    int b = i / 25;
    int o = (i - b * 25) * 4;
    float4 s = *(const float4*)(g_bc + o);
    #pragma unroll
    for (int sl = 0; sl < NSLICE; sl++) {
        float4 p = *(const float4*)(g_part + ((size_t)sl * BATCH + b) * PPITCH + o);
        s.x += p.x; s.y += p.y; s.z += p.z; s.w += p.w;
    }
    *(float4*)(out + (size_t)b * OUTPUT + o) = s;
}

// ---------------- launch ---------------------------------------------------
extern "C" void kernel_launch(void* const* d_in, const int* in_sizes, int n_in,
                              void* d_out, int out_size) {
    const int*   words = (const int*)  d_in[0];
    const float* W1    = (const float*)d_in[1];
    const float* b1    = (const float*)d_in[2];
    const float* W2    = (const float*)d_in[3];
    const float* b2    = (const float*)d_in[4];

    cudaFuncSetAttribute(wc_gemm,
        cudaFuncAttributeMaxDynamicSharedMemorySize, 3 * WC_STG);
    cudaFuncSetAttribute(main_gemm,
        cudaFuncAttributeMaxDynamicSharedMemorySize, MG_SMEM);

    prelude_kernel<<<NB_TOTAL, 256>>>(words, b1, W2, b2);
    wc_gemm<<<K_PAD / 64, 256, 3 * WC_STG>>>(W1);
    main_gemm<<<dim3(32, NSLICE), 128, MG_SMEM>>>();
    reduce_kernel<<<(BATCH * 25) / 256, 256>>>((float*)d_out);
}

// round 11
// speedup vs baseline: 1.1820x; 1.1253x over previous
#include <cuda_runtime.h>
#include <cuda_fp16.h>
#include <cstdint>

#define CHARS   10000
#define HIDDEN  1024
#define OUTPUT  100
#define BATCH   4096
#define MAXLEN  2048

#define K_PAD   10240
#define NPAD    128
#define PPITCH  104
#define NSLICE  8
#define K_SLICE (K_PAD / NSLICE)      // 1280
#define NCHUNK_MAIN (K_SLICE / 64)    // 20
#define NCHUNK_WC   (HIDDEN / 64)     // 16

// ---------------- device scratch (static; allocations are banned) --------
__device__ __half  g_hist[(size_t)BATCH * K_PAD];           // 84 MB
__device__ __half  g_w2f[(size_t)NPAD * HIDDEN];            // 256 KB
__device__ __half  g_wcf[(size_t)NPAD * K_PAD];             // 2.6 MB
__device__ float   g_part[(size_t)BATCH * NSLICE * PPITCH]; // 13.6 MB  [b][sl][o]
__device__ __align__(16) float g_bc[OUTPUT];

// ---------------- PTX helpers (portable sm_80-class only) ----------------
__device__ __forceinline__ uint32_t smem_u32(const void* p) {
    uint32_t a;
    asm("{ .reg .u64 t; cvta.to.shared.u64 t, %1; cvt.u32.u64 %0, t; }"
        : "=r"(a) : "l"(p));
    return a;
}

__device__ __forceinline__ void cp16(uint32_t s, const void* g) {
    asm volatile("cp.async.cg.shared.global [%0], [%1], 16;" :: "r"(s), "l"(g));
}
__device__ __forceinline__ void cp16ca(uint32_t s, const void* g) {
    asm volatile("cp.async.ca.shared.global [%0], [%1], 16;" :: "r"(s), "l"(g));
}
#define CP_COMMIT() asm volatile("cp.async.commit_group;" ::: "memory")
#define CP_WAIT1()  asm volatile("cp.async.wait_group 1;"  ::: "memory")

__device__ __forceinline__ void ldsm4(uint32_t* r, uint32_t a) {
    asm volatile("ldmatrix.sync.aligned.m8n8.x4.shared.b16 {%0,%1,%2,%3}, [%4];"
        : "=r"(r[0]), "=r"(r[1]), "=r"(r[2]), "=r"(r[3]) : "r"(a));
}
__device__ __forceinline__ void ldsm4t(uint32_t* r, uint32_t a) {
    asm volatile("ldmatrix.sync.aligned.m8n8.x4.trans.shared.b16 {%0,%1,%2,%3}, [%4];"
        : "=r"(r[0]), "=r"(r[1]), "=r"(r[2]), "=r"(r[3]) : "r"(a));
}

// D(16x8,f32) += A(16x16,f16) @ B(16x8,f16)
__device__ __forceinline__ void mma_f16(float* c, const uint32_t* a, const uint32_t* b) {
    asm volatile(
        "mma.sync.aligned.m16n8k16.row.col.f32.f16.f16.f32 "
        "{%0,%1,%2,%3}, {%4,%5,%6,%7}, {%8,%9}, {%0,%1,%2,%3};"
        : "+f"(c[0]), "+f"(c[1]), "+f"(c[2]), "+f"(c[3])
        : "r"(a[0]), "r"(a[1]), "r"(a[2]), "r"(a[3]), "r"(b[0]), "r"(b[1]));
}

#define PA 144     // smem pitch (bytes) for 64-col 16-bit rows, +8 elem pad

// ---------------- kernel 1: prelude (hist + W2 conv + bc) ----------------
#define NB_HIST 4096
#define NB_W2   512
#define NB_BC   13
#define NB_TOTAL (NB_HIST + NB_W2 + NB_BC)

__global__ void __launch_bounds__(256) prelude_kernel(
        const int* __restrict__ words, const float* __restrict__ b1,
        const float* __restrict__ W2,  const float* __restrict__ b2) {
    __shared__ unsigned cnt[K_PAD / 2];
    const int bid = blockIdx.x, tid = threadIdx.x;

    if (bid < NB_HIST) {
        for (int i = tid; i < K_PAD / 2; i += 256) cnt[i] = 0u;
        __syncthreads();
        const int* w = words + (size_t)bid * MAXLEN;
        #pragma unroll 8
        for (int j = tid; j < MAXLEN; j += 256) {
            unsigned c = (unsigned)w[j];
            atomicAdd(&cnt[c >> 1], 1u << ((c & 1u) * 16));
        }
        __syncthreads();
        __half2* out = (__half2*)(g_hist + (size_t)bid * K_PAD);
        for (int i = tid; i < K_PAD / 2; i += 256) {
            unsigned v = cnt[i];
            out[i] = __floats2half2_rn((float)(v & 0xFFFFu), (float)(v >> 16));
        }
    } else if (bid < NB_HIST + NB_W2) {
        unsigned i = (bid - NB_HIST) * 256u + tid;           // over 128*1024
        unsigned o = i >> 10;
        float v = (o < OUTPUT) ? W2[(size_t)o * HIDDEN + (i & 1023u)] : 0.f;
        g_w2f[i] = __float2half_rn(v);
    } else {
        int o = (bid - NB_HIST - NB_W2) * 8 + (tid >> 5);
        if (o < OUTPUT) {
            int lane = tid & 31;
            const float* w = W2 + (size_t)o * HIDDEN;
            float s = 0.f;
            #pragma unroll 8
            for (int h = lane; h < HIDDEN; h += 32) s += w[h] * b1[h];
            #pragma unroll
            for (int off = 16; off; off >>= 1)
                s += __shfl_xor_sync(0xFFFFFFFFu, s, off);
            if (lane == 0) g_bc[o] = b2[o] + s;
        }
    }
}

// ---------------- kernel 2: Wc = W2 @ W1 (fused W1 fp32->fp16) -----------
// CTA 128 o x 64 c, K=1024 (16 chunks). grid 160. 8 warps (4m x 2n).
#define WC_A 0
#define WC_B 18432
#define WC_STG 27648

__global__ void __launch_bounds__(256, 2) wc_gemm(const float* __restrict__ W1) {
    extern __shared__ char smn[];
    uint32_t sb = smem_u32(smn);
    const int tid = threadIdx.x, lid = tid & 31, wid = tid >> 5;
    const int wm = wid >> 1, wn = wid & 1, gid = lid >> 2, t4 = lid & 3;
    const int c0 = blockIdx.x * 64;

    const int arow = tid >> 1;
    const int acol = (tid & 1) * 64;
    const char* gA = (const char*)(g_w2f + (size_t)arow * HIDDEN) + acol;
    const uint32_t sA = sb + WC_A + arow * PA + acol;

    const int brow = tid >> 2;
    const int bcole = (tid & 3) * 16;
    const uint32_t oB = WC_B + brow * PA + bcole * 2;

    float4 rb[4];
    auto loadB = [&](int it) {
        const float* p = W1 + (size_t)(it * 64 + brow) * CHARS + c0 + bcole;
        #pragma unroll
        for (int i = 0; i < 4; i++) {
            int c = c0 + bcole + i * 4;
            rb[i] = (c < CHARS) ? *(const float4*)(p + i * 4)
                                : make_float4(0.f, 0.f, 0.f, 0.f);
        }
    };
    auto stsB = [&](int slot) {
        uint32_t so = slot * WC_STG;
        #pragma unroll
        for (int j = 0; j < 2; j++) {
            __half2 h0 = __floats2half2_rn(rb[2*j].x,   rb[2*j].y);
            __half2 h1 = __floats2half2_rn(rb[2*j].z,   rb[2*j].w);
            __half2 h2 = __floats2half2_rn(rb[2*j+1].x, rb[2*j+1].y);
            __half2 h3 = __floats2half2_rn(rb[2*j+1].z, rb[2*j+1].w);
            *(uint4*)(smn + oB + so + j * 16) =
                make_uint4(*(uint32_t*)&h0, *(uint32_t*)&h1,
                           *(uint32_t*)&h2, *(uint32_t*)&h3);
        }
    };
    auto cpA = [&](int it, int slot) {
        if (it < NCHUNK_WC) {
            uint32_t so = slot * WC_STG;
            size_t ka = (size_t)it * 128;
            #pragma unroll
            for (int i = 0; i < 4; i++) cp16(sA + so + i * 16, gA + ka + i * 16);
        }
        CP_COMMIT();
    };

    float acc[2][4][4];
    #pragma unroll
    for (int mb = 0; mb < 2; mb++)
        #pragma unroll
        for (int nf = 0; nf < 4; nf++)
            #pragma unroll
            for (int e = 0; e < 4; e++) acc[mb][nf][e] = 0.f;

    loadB(0); stsB(0);
    loadB(1);
    cpA(0, 0); cpA(1, 1);

    int sc = 0, sn = 2;
    for (int it = 0; it < NCHUNK_WC; ++it) {
        uint32_t st = sb + sc * WC_STG;
        CP_WAIT1();
        __syncthreads();
        if (it + 1 < NCHUNK_WC) stsB((it + 1) % 3);
        if (it + 2 < NCHUNK_WC) loadB(it + 2);
        cpA(it + 2, sn);
        #pragma unroll
        for (int ks = 0; ks < 4; ks++) {
            uint32_t a[2][4];
            #pragma unroll
            for (int mb = 0; mb < 2; mb++) {
                uint32_t r = (wm * 32 + mb * 16 + (lid & 15));
                ldsm4(a[mb], st + WC_A + r * PA + ks * 32 + (lid >> 4) * 16);
            }
            #pragma unroll
            for (int nq = 0; nq < 2; nq++) {
                uint32_t r = ks * 16 + ((lid >> 3) & 1) * 8 + (lid & 7);
                uint32_t cb = (wn * 32 + nq * 16) * 2 + ((lid >> 4) & 1) * 16;
                uint32_t b[4];
                ldsm4t(b, st + WC_B + r * PA + cb);
                #pragma unroll
                for (int mb = 0; mb < 2; mb++)
                    #pragma unroll
                    for (int f = 0; f < 2; f++)
                        mma_f16(acc[mb][nq * 2 + f], a[mb], &b[f * 2]);
            }
        }
        sc = (sc == 2) ? 0 : sc + 1;
        sn = (sn == 2) ? 0 : sn + 1;
    }

    #pragma unroll
    for (int mb = 0; mb < 2; mb++)
        #pragma unroll
        for (int nf = 0; nf < 4; nf++) {
            int o = wm * 32 + mb * 16 + gid;
            int c = c0 + wn * 32 + nf * 8 + t4 * 2;
            *(__half2*)(g_wcf + (size_t)o * K_PAD + c) =
                __floats2half2_rn(acc[mb][nf][0], acc[mb][nf][1]);
            *(__half2*)(g_wcf + (size_t)(o + 8) * K_PAD + c) =
                __floats2half2_rn(acc[mb][nf][2], acc[mb][nf][3]);
        }
}

// ---------------- kernel 3: main GEMM  part = hist @ Wc^T (fp16) ---------
// CTA 128 m x 112 n (covers OUTPUT=100), 128 threads = 4 warps.
// wn=0 warps: 64x64; wn=1 warps: 64x48 (3 n-quads). 3 stages, 1 barrier/iter.
#define NB      112                    // B rows staged
#define MG_A    0                      // 3 x 18432
#define MG_B    55296                  // 3 x 16128
#define B_STG   16128                  // 112 * 144
#define MG_SMEM (55296 + 3 * B_STG)    // 103680

__global__ void __launch_bounds__(128, 2) main_gemm() {
    extern __shared__ char smn[];
    uint32_t sb = smem_u32(smn);
    const int tid = threadIdx.x, lid = tid & 31, wid = tid >> 5;
    const int wm = wid >> 1, wn = wid & 1, gid = lid >> 2, t4 = lid & 3;
    const int m0 = blockIdx.x * 128;
    const int kbase = blockIdx.y * K_SLICE;
    const int nqmax = 4 - wn;          // 4 n-quads for wn=0, 3 for wn=1

    // A cp.async: thread per m-row, 128B per chunk
    const char* gA = (const char*)(g_hist + (size_t)(m0 + tid) * K_PAD + kbase);
    const uint32_t sA = sb + MG_A + tid * PA;
    // B cp.async: 112 rows x 128B = 896 cp16 = 7 per thread
    const int rb8  = tid >> 3;                 // row offset within 16-group
    const int bcol = (tid & 7) * 16;
    const char* gBc = (const char*)g_wcf + (size_t)kbase * 2 + bcol;
    const uint32_t sBb = sb + MG_B + bcol;

    auto issue = [&](int it, int s) {
        if (it < NCHUNK_MAIN) {
            size_t ko = (size_t)it * 128;
            uint32_t soA = s * 18432, soB = s * B_STG;
            #pragma unroll
            for (int i = 0; i < 8; i++)
                cp16(sA + soA + i * 16, gA + ko + i * 16);
            #pragma unroll
            for (int i = 0; i < 7; i++) {
                int row = i * 16 + rb8;
                cp16ca(sBb + soB + row * PA,
                       gBc + (size_t)row * (K_PAD * 2) + ko);
            }
        }
        CP_COMMIT();
    };

    float acc[4][8][4];
    #pragma unroll
    for (int mb = 0; mb < 4; mb++)
        #pragma unroll
        for (int nf = 0; nf < 8; nf++)
            #pragma unroll
            for (int e = 0; e < 4; e++) acc[mb][nf][e] = 0.f;

    const uint32_t aoff = (wm * 64 + (lid & 15)) * PA + (lid >> 4) * 16;
    const uint32_t boff = (wn * 64 + ((lid >> 4) & 1) * 8 + (lid & 7)) * PA
                          + ((lid >> 3) & 1) * 16;

    issue(0, 0); issue(1, 1);
    int sc = 0, sn = 2;
    for (int it = 0; it < NCHUNK_MAIN; ++it) {
        uint32_t stA = sb + MG_A + sc * 18432;
        uint32_t stB = sb + MG_B + sc * B_STG;
        CP_WAIT1();
        __syncthreads();
        issue(it + 2, sn);
        #pragma unroll
        for (int ks = 0; ks < 4; ks++) {
            uint32_t ko = ks * 32;
            uint32_t a[4][4], b[4][4];
            #pragma unroll
            for (int mb = 0; mb < 4; mb++)
                ldsm4(a[mb], stA + aoff + mb * 16 * PA + ko);
            #pragma unroll
            for (int nq = 0; nq < 4; nq++)
                if (nq < nqmax)
                    ldsm4(b[nq], stB + boff + nq * 16 * PA + ko);
            #pragma unroll
            for (int nq = 0; nq < 4; nq++)
                if (nq < nqmax)
                    #pragma unroll
                    for (int mb = 0; mb < 4; mb++)
                        #pragma unroll
                        for (int f = 0; f < 2; f++)
                            mma_f16(acc[mb][nq * 2 + f], a[mb], &b[nq][f * 2]);
        }
        sc = (sc == 2) ? 0 : sc + 1;
        sn = (sn == 2) ? 0 : sn + 1;
    }

    // epilogue: g_part layout [b][sl][PPITCH]
    #pragma unroll
    for (int mb = 0; mb < 4; mb++)
        #pragma unroll
        for (int nf = 0; nf < 8; nf++) {
            int r = m0 + wm * 64 + mb * 16 + gid;
            int c = wn * 64 + nf * 8 + t4 * 2;
            if (c < OUTPUT) {
                float* p0 = g_part + ((size_t)r * NSLICE + blockIdx.y) * PPITCH + c;
                float* p1 = g_part + ((size_t)(r + 8) * NSLICE + blockIdx.y) * PPITCH + c;
                *(float2*)p0 = make_float2(acc[mb][nf][0], acc[mb][nf][1]);
                *(float2*)p1 = make_float2(acc[mb][nf][2], acc[mb][nf][3]);
            }
        }
}

// ---------------- kernel 4: split-K reduce + bias (warp per row) ---------
// partials for one row are contiguous (8 x 416 B); lanes 0-24 cover 100 cols.
__global__ void __launch_bounds__(256) reduce_kernel(float* __restrict__ out) {
    int w = threadIdx.x >> 5, lane = threadIdx.x & 31;
    int b = blockIdx.x * 8 + w;
    if (lane < 25) {
        int o = lane * 4;
        float4 s = *(const float4*)(g_bc + o);
        const float* pb = g_part + (size_t)b * NSLICE * PPITCH + o;
        #pragma unroll
        for (int sl = 0; sl < NSLICE; sl++) {
            float4 p = *(const float4*)(pb + sl * PPITCH);
            s.x += p.x; s.y += p.y; s.z += p.z; s.w += p.w;
        }
        *(float4*)(out + (size_t)b * OUTPUT + o) = s;
    }
}

// ---------------- launch ---------------------------------------------------
extern "C" void kernel_launch(void* const* d_in, const int* in_sizes, int n_in,
                              void* d_out, int out_size) {
    const int*   words = (const int*)  d_in[0];
    const float* W1    = (const float*)d_in[1];
    const float* b1    = (const float*)d_in[2];
    const float* W2    = (const float*)d_in[3];
    const float* b2    = (const float*)d_in[4];

    cudaFuncSetAttribute(wc_gemm,
        cudaFuncAttributeMaxDynamicSharedMemorySize, 3 * WC_STG);
    cudaFuncSetAttribute(main_gemm,
        cudaFuncAttributeMaxDynamicSharedMemorySize, MG_SMEM);

    prelude_kernel<<<NB_TOTAL, 256>>>(words, b1, W2, b2);
    wc_gemm<<<K_PAD / 64, 256, 3 * WC_STG>>>(W1);
    main_gemm<<<dim3(32, NSLICE), 128, MG_SMEM>>>();
    reduce_kernel<<<BATCH / 8, 256>>>((float*)d_out);
}